// round 6
// baseline (speedup 1.0000x reference)
#include <cuda_runtime.h>

#define TT   512
#define BB   2048
#define NTAG 16
#define LOG2E 1.4426950408889634f

// scratch: h sequence (T, B, 4) fp32 = 16.8 MB
__device__ float g_h[(size_t)TT * BB * 4];

typedef unsigned long long u64;

__device__ __forceinline__ float rcp_ap(float x)  { float r; asm("rcp.approx.f32 %0, %1;"  : "=f"(r) : "f"(x)); return r; }
__device__ __forceinline__ float ex2_ap(float x)  { float r; asm("ex2.approx.f32 %0, %1;"  : "=f"(r) : "f"(x)); return r; }
__device__ __forceinline__ float lg2_ap(float x)  { float r; asm("lg2.approx.f32 %0, %1;"  : "=f"(r) : "f"(x)); return r; }
__device__ __forceinline__ float cos_ap(float x)  { float r; asm("cos.approx.f32 %0, %1;"  : "=f"(r) : "f"(x)); return r; }

// packed f32x2 helpers (sm_100+)
__device__ __forceinline__ u64 pk(float lo, float hi) {
    u64 r; asm("mov.b64 %0, {%1, %2};" : "=l"(r) : "f"(lo), "f"(hi)); return r;
}
__device__ __forceinline__ void upk(u64 v, float& lo, float& hi) {
    asm("mov.b64 {%0, %1}, %2;" : "=f"(lo), "=f"(hi) : "l"(v));
}
__device__ __forceinline__ u64 fma2(u64 a, u64 b, u64 c) {
    u64 d; asm("fma.rn.f32x2 %0, %1, %2, %3;" : "=l"(d) : "l"(a), "l"(b), "l"(c)); return d;
}

// Pade[5/4] tanh: tanh(u) = u*(q^2+105q+945)/(15q^2+420q+945), q=u^2.
// err <= ~5e-8 on [-1,1]. Gate value: v = fma(A, tanh(m*e), B).
__device__ __forceinline__ float gpade(float e, float m, float A, float B) {
    float u = m * e;
    float q = u * u;
    float n = fmaf(q + 105.0f, q, 945.0f) * u;
    float d = fmaf(fmaf(q, 15.0f, 420.0f), q, 945.0f);
    return fmaf(A, n * rcp_ap(d), B);
}

// per-chain recurrent state
struct CS {
    float s0[8], s1[8];   // 2-deep x prefetch ring
    u64 xp01, xp23;       // xacc (packed) for current step
    float h0, h1, h2, h3; // hidden (replicated across quad)
    float cx;             // own-wire cell state
};

__device__ __forceinline__ void load8(const float* __restrict__ x, int t, int b, float (&s)[8]) {
    const float4* p = (const float4*)x + ((size_t)t * BB + b) * 2;
    float4 a = p[0], c = p[1];
    s[0]=a.x; s[1]=a.y; s[2]=a.z; s[3]=a.w; s[4]=c.x; s[5]=c.y; s[6]=c.z; s[7]=c.w;
}

__device__ __forceinline__ void xacc8(const float (&s)[8],
    const u64* wxp01, const u64* wxp23, u64 th01, u64 th23, u64& o01, u64& o23)
{
    u64 p01 = th01, p23 = th23;
#pragma unroll
    for (int d = 0; d < 8; d++) {
        u64 xd = pk(s[d], s[d]);
        p01 = fma2(xd, wxp01[d], p01);
        p23 = fma2(xd, wxp23[d], p23);
    }
    o01 = p01; o23 = p23;
}

// One LSTM step for one chain. NSLOT = ring slot used for NEXT step's xacc
// (and refilled with x[t+3]). Must be a compile-time constant.
template<int NSLOT>
__device__ __forceinline__ void step(CS& S, int t, int b,
    const float* __restrict__ x,
    const u64* whp01, const u64* whp23,
    const u64* wxp01, const u64* wxp23, u64 th01, u64 th23,
    float gm, float gA, float gB, bool hi1, bool hi2, float* hout)
{
    // ---- pre = xacc + Wh*h (packed) ; c = cos(pre)  [h-critical path] ----
    u64 hb0 = pk(S.h0, S.h0), hb1 = pk(S.h1, S.h1), hb2 = pk(S.h2, S.h2), hb3 = pk(S.h3, S.h3);
    u64 p01 = fma2(hb0, whp01[0], S.xp01);
    p01 = fma2(hb1, whp01[1], p01);
    p01 = fma2(hb2, whp01[2], p01);
    p01 = fma2(hb3, whp01[3], p01);
    u64 p23 = fma2(hb0, whp23[0], S.xp23);
    p23 = fma2(hb1, whp23[1], p23);
    p23 = fma2(hb2, whp23[2], p23);
    p23 = fma2(hb3, whp23[3], p23);
    float pre0, pre1, pre2, pre3;
    upk(p01, pre0, pre1); upk(p23, pre2, pre3);
    float c0 = cos_ap(pre0), c1 = cos_ap(pre1), c2 = cos_ap(pre2), c3 = cos_ap(pre3);

    // ---- off-path: xacc for t+1 from ring slot, then refill slot with x[t+3] ----
    if (NSLOT == 0) xacc8(S.s0, wxp01, wxp23, th01, th23, S.xp01, S.xp23);
    else            xacc8(S.s1, wxp01, wxp23, th01, th23, S.xp01, S.xp23);
    int tp = t + 3; if (tp > TT - 1) tp = TT - 1;
    if (NSLOT == 0) load8(x, tp, b, S.s0);
    else            load8(x, tp, b, S.s1);

    // ---- expvals: e0=c1c2c3, e1=c0c1, e2=e1c2, e3=e1t23 ----
    float t23 = c2 * c3;
    float e1  = c0 * c1;
    float e0  = c1 * t23;
    float e2  = e1 * c2;
    float e3  = e1 * t23;

    // ---- gate nonlinearity (Pade, 1 MUFU each) ----
    float v0 = gpade(e0, gm, gA, gB);
    float v1 = gpade(e1, gm, gA, gB);
    float v2 = gpade(e2, gm, gA, gB);
    float v3 = gpade(e3, gm, gA, gB);

    // ---- butterfly 4x4 transpose: lane g gets (F,I,G,O) of wire g ----
    float s0 = hi2 ? v0 : v2;
    float s1 = hi2 ? v1 : v3;
    float r0 = __shfl_xor_sync(0xffffffffu, s0, 2);
    float r1 = __shfl_xor_sync(0xffffffffu, s1, 2);
    float a0 = hi2 ? r0 : v0;
    float a1 = hi2 ? r1 : v1;
    float a2 = hi2 ? v2 : r0;
    float a3 = hi2 ? v3 : r1;
    float t0 = hi1 ? a0 : a1;
    float t1 = hi1 ? a2 : a3;
    float q0 = __shfl_xor_sync(0xffffffffu, t0, 1);
    float q1 = __shfl_xor_sync(0xffffffffu, t1, 1);
    float F = hi1 ? q0 : a0;
    float I = hi1 ? a1 : q0;
    float G = hi1 ? q1 : a2;
    float O = hi1 ? a3 : q1;

    // ---- single-wire combine (wire g) ----
    float nc = fmaf(F, S.cx, I * G);
    S.cx = nc;
    float E  = ex2_ap(nc * (2.0f * LOG2E));   // tanh(cx) = 1 - 2/(exp(2cx)+1)
    float rr = rcp_ap(E + 1.0f);
    float tc = fmaf(-2.0f, rr, 1.0f);
    float h  = O * tc;

    hout[(size_t)t * (BB * 4)] = h;

    // ---- butterfly allgather of h across the quad ----
    float hp  = __shfl_xor_sync(0xffffffffu, h, 1);
    float hA0 = hi1 ? hp : h;
    float hA1 = hi1 ? h  : hp;
    float sA0 = __shfl_xor_sync(0xffffffffu, hA0, 2);
    float sA1 = __shfl_xor_sync(0xffffffffu, hA1, 2);
    S.h0 = hi2 ? sA0 : hA0;
    S.h1 = hi2 ? sA1 : hA1;
    S.h2 = hi2 ? hA0 : sA0;
    S.h3 = hi2 ? hA1 : sA1;
}

// ---------------------------------------------------------------------------
// Kernel A: LSTM recurrence, 2 chains interleaved per thread (latency hiding).
// Quad q (4 lanes, one per gate) serves chains q and q+1024.
// ---------------------------------------------------------------------------
__global__ void __launch_bounds__(32, 1)
recur_kernel(const float* __restrict__ x,
             const float* __restrict__ w_gates,
             const float* __restrict__ b_gates,
             const float* __restrict__ rx_theta)
{
    const int tid = blockIdx.x * 32 + threadIdx.x;   // 0..4095
    const int q   = tid >> 2;                        // quad 0..1023
    const int g   = tid & 3;                         // gate (f,i,g,o)
    const bool hi1 = (g & 1), hi2 = (g & 2);
    const int bA = q, bB = q + 1024;

    // per-lane weights (shared by both chains): w_gates (4,4,12)
    float wx[4][8], wh[4][4], th[4];
#pragma unroll
    for (int k = 0; k < 4; k++) {
#pragma unroll
        for (int d = 0; d < 8; d++) wx[k][d] = w_gates[g*48 + k*12 + d];
#pragma unroll
        for (int j = 0; j < 4; j++) wh[k][j] = w_gates[g*48 + k*12 + 8 + j];
        th[k] = b_gates[g*4 + k] + rx_theta[g*4 + k];
    }
    u64 wxp01[8], wxp23[8], whp01[4], whp23[4];
#pragma unroll
    for (int d = 0; d < 8; d++) { wxp01[d] = pk(wx[0][d], wx[1][d]); wxp23[d] = pk(wx[2][d], wx[3][d]); }
#pragma unroll
    for (int j = 0; j < 4; j++) { whp01[j] = pk(wh[0][j], wh[1][j]); whp23[j] = pk(wh[2][j], wh[3][j]); }
    u64 th01 = pk(th[0], th[1]), th23 = pk(th[2], th[3]);

    // gate type constants: lane 2 = tanh(e); others sigmoid(e) = 0.5+0.5*tanh(e/2)
    const float gm = (g == 2) ? 1.0f : 0.5f;
    const float gA = (g == 2) ? 1.0f : 0.5f;
    const float gB = (g == 2) ? 0.0f : 0.5f;

    CS A, B;
    A.h0=A.h1=A.h2=A.h3=0.f; A.cx=0.f;
    B.h0=B.h1=B.h2=B.h3=0.f; B.cx=0.f;

    // prologue: ring holds x[t+1] in slot (t+1)&1 at entry to step t
    load8(x, 0, bA, A.s0); load8(x, 1, bA, A.s1);
    load8(x, 0, bB, B.s0); load8(x, 1, bB, B.s1);
    xacc8(A.s0, wxp01, wxp23, th01, th23, A.xp01, A.xp23);
    xacc8(B.s0, wxp01, wxp23, th01, th23, B.xp01, B.xp23);
    load8(x, 2, bA, A.s0);
    load8(x, 2, bB, B.s0);

    float* houtA = g_h + (size_t)bA * 4 + g;
    float* houtB = g_h + (size_t)bB * 4 + g;

    for (int t = 0; t < TT; t += 2) {
        step<1>(A, t,   bA, x, whp01, whp23, wxp01, wxp23, th01, th23, gm, gA, gB, hi1, hi2, houtA);
        step<1>(B, t,   bB, x, whp01, whp23, wxp01, wxp23, th01, th23, gm, gA, gB, hi1, hi2, houtB);
        step<0>(A, t+1, bA, x, whp01, whp23, wxp01, wxp23, th01, th23, gm, gA, gB, hi1, hi2, houtA);
        step<0>(B, t+1, bB, x, whp01, whp23, wxp01, wxp23, th01, th23, gm, gA, gB, hi1, hi2, houtB);
    }
}

// ---------------------------------------------------------------------------
// Kernel B: logits + log_softmax. 2 threads per row (8 tags each) to cut
// register pressure (was regs=127, occ 21%); softmax joined via 2 shfl_xor.
// ---------------------------------------------------------------------------
__global__ void __launch_bounds__(256)
out_kernel(const float* __restrict__ w_tag,
           const float* __restrict__ b_tag,
           float* __restrict__ out)
{
    int gt   = blockIdx.x * 256 + threadIdx.x;   // 0 .. 2*NITEM-1
    int row  = gt >> 1;
    int half = gt & 1;

    const float4* wt = (const float4*)w_tag;     // 16 rows of float4
    float4 w[8]; float bt[8];
#pragma unroll
    for (int j = 0; j < 8; j++) { w[j] = wt[half*8 + j]; bt[j] = b_tag[half*8 + j]; }

    float4 hv = ((const float4*)g_h)[row];
    float lg[8];
#pragma unroll
    for (int j = 0; j < 8; j++)
        lg[j] = fmaf(w[j].w, hv.w, fmaf(w[j].z, hv.z, fmaf(w[j].y, hv.y, fmaf(w[j].x, hv.x, bt[j]))));

    float m = lg[0];
#pragma unroll
    for (int j = 1; j < 8; j++) m = fmaxf(m, lg[j]);
    m = fmaxf(m, __shfl_xor_sync(0xffffffffu, m, 1));

    float s = 0.f;
#pragma unroll
    for (int j = 0; j < 8; j++) s += ex2_ap((lg[j] - m) * LOG2E);
    s += __shfl_xor_sync(0xffffffffu, s, 1);

    float ls = fmaf(lg2_ap(s), 0.6931471805599453f, m);

    float4* o4 = (float4*)out;
    o4[(size_t)row*4 + half*2 + 0] = make_float4(lg[0]-ls, lg[1]-ls, lg[2]-ls, lg[3]-ls);
    o4[(size_t)row*4 + half*2 + 1] = make_float4(lg[4]-ls, lg[5]-ls, lg[6]-ls, lg[7]-ls);
}

extern "C" void kernel_launch(void* const* d_in, const int* in_sizes, int n_in,
                              void* d_out, int out_size)
{
    const float* x        = (const float*)d_in[0];
    const float* w_gates  = (const float*)d_in[1];
    const float* b_gates  = (const float*)d_in[2];
    const float* rx_theta = (const float*)d_in[3];
    const float* w_tag    = (const float*)d_in[4];
    const float* b_tag    = (const float*)d_in[5];

    recur_kernel<<<128, 32>>>(x, w_gates, b_gates, rx_theta);   // 4096 threads, 2 chains/thread
    out_kernel<<<8192, 256>>>(w_tag, b_tag, (float*)d_out);     // 2 threads per (t,b) row
}

// round 7
// speedup vs baseline: 1.5259x; 1.5259x over previous
#include <cuda_runtime.h>

#define TT   512
#define BB   2048
#define NTAG 16
#define LOG2E 1.4426950408889634f

// scratch: h sequence (T, B, 4) fp32 = 16.8 MB
__device__ float g_h[(size_t)TT * BB * 4];

__device__ __forceinline__ float rcp_ap(float x)  { float r; asm("rcp.approx.f32 %0, %1;"  : "=f"(r) : "f"(x)); return r; }
__device__ __forceinline__ float ex2_ap(float x)  { float r; asm("ex2.approx.f32 %0, %1;"  : "=f"(r) : "f"(x)); return r; }
__device__ __forceinline__ float lg2_ap(float x)  { float r; asm("lg2.approx.f32 %0, %1;"  : "=f"(r) : "f"(x)); return r; }
__device__ __forceinline__ float cos_ap(float x)  { float r; asm("cos.approx.f32 %0, %1;"  : "=f"(r) : "f"(x)); return r; }

// Pade[5/4] tanh core: tanh(u) = u*(q^2+105q+945)/(15q^2+420q+945), q=u^2.
// |err| <= ~5e-8 on |u|<=1 (gate inputs are products of cosines, |u|<=1).
__device__ __forceinline__ float tanh_pade(float u) {
    float q = u * u;
    float n = fmaf(q + 105.0f, q, 945.0f) * u;
    float d = fmaf(fmaf(q, 15.0f, 420.0f), q, 945.0f);
    return n * rcp_ap(d);
}

// ---------------------------------------------------------------------------
// Kernel A: the LSTM recurrence. 4 lanes per batch chain (one per gate g).
// Lane g computes pre[g][0..3], c=cos, e-products, gate nonlinearity; the four
// gate vectors are exchanged with shfl (width=4); cx/h are replicated per lane.
// Structure identical to the R4 best-known kernel except:
//   - 64-thread blocks (warps spread over 2 SMSPs instead of all piling on SMSP0)
//   - gate nonlinearity via Pade tanh (1 MUFU) with prescale folded into c1:
//       sigmoid(e) = 0.5 + 0.5*tanh(e/2)  -> scale c1 by 0.5, A=0.5, B=0.5
//       tanh(e)                           -> scale c1 by 1.0, A=1.0, B=0.0
// ---------------------------------------------------------------------------
__global__ void __launch_bounds__(64, 1)
recur_kernel(const float* __restrict__ x,
             const float* __restrict__ w_gates,
             const float* __restrict__ b_gates,
             const float* __restrict__ rx_theta)
{
    const int tid = blockIdx.x * 64 + threadIdx.x;   // 0..8191
    const int b   = tid >> 2;                        // batch chain 0..2047
    const int g   = tid & 3;                         // gate (f,i,g,o)

    // per-lane weights: w_gates layout (4,4,12): [g*48 + k*12 + d]
    float wx[4][8], wh[4][4], th[4];
#pragma unroll
    for (int k = 0; k < 4; k++) {
#pragma unroll
        for (int d = 0; d < 8; d++) wx[k][d] = w_gates[g*48 + k*12 + d];
#pragma unroll
        for (int j = 0; j < 4; j++) wh[k][j] = w_gates[g*48 + k*12 + 8 + j];
        th[k] = b_gates[g*4 + k] + rx_theta[g*4 + k];
    }
    // lane 2 is the tanh gate; lanes 0,1,3 are sigmoid gates
    const float gm = (g == 2) ? 1.0f : 0.5f;   // folded into c1
    const float gA = (g == 2) ? 1.0f : 0.5f;
    const float gB = (g == 2) ? 0.0f : 0.5f;

    float h0 = 0.f, h1 = 0.f, h2 = 0.f, h3 = 0.f;
    float cx[4] = {0.f, 0.f, 0.f, 0.f};

    const float4* xp = (const float4*)x;             // (t*BB + b)*2 indexing
    float4 xa[4], xb[4];                             // 4-deep prefetch ring
#pragma unroll
    for (int p = 0; p < 4; p++) {
        size_t i = ((size_t)p * BB + b) * 2;
        xa[p] = xp[i]; xb[p] = xp[i + 1];
    }

    // x-part of pre for t=0 (one step ahead); consumes slot 0
    float xacc[4];
    {
        float xv[8] = {xa[0].x, xa[0].y, xa[0].z, xa[0].w,
                       xb[0].x, xb[0].y, xb[0].z, xb[0].w};
#pragma unroll
        for (int k = 0; k < 4; k++) {
            float q = fmaf(xv[0], wx[k][0], th[k]);
            q = fmaf(xv[1], wx[k][1], q); q = fmaf(xv[2], wx[k][2], q);
            q = fmaf(xv[3], wx[k][3], q); q = fmaf(xv[4], wx[k][4], q);
            q = fmaf(xv[5], wx[k][5], q); q = fmaf(xv[6], wx[k][6], q);
            xacc[k] = fmaf(xv[7], wx[k][7], q);
        }
    }
    // slot 0 is next used at t=3 to build xacc(t=4) -> must hold x[4]
    {
        size_t i4 = ((size_t)4 * BB + b) * 2;
        xa[0] = xp[i4]; xb[0] = xp[i4 + 1];
    }

    float4* hout = (float4*)g_h;

#pragma unroll 4
    for (int t = 0; t < TT; t++) {
        // ---- pre = xacc + Wh·h ; c = cos(pre) (h-critical path) ----
        float c0, c1, c2, c3;
        {
            float s0, s1;
            s0 = fmaf(h1, wh[0][1], fmaf(h0, wh[0][0], xacc[0]));
            s1 = fmaf(h3, wh[0][3], h2 * wh[0][2]);
            c0 = cos_ap(s0 + s1);
            s0 = fmaf(h1, wh[1][1], fmaf(h0, wh[1][0], xacc[1]));
            s1 = fmaf(h3, wh[1][3], h2 * wh[1][2]);
            c1 = cos_ap(s0 + s1);
            s0 = fmaf(h1, wh[2][1], fmaf(h0, wh[2][0], xacc[2]));
            s1 = fmaf(h3, wh[2][3], h2 * wh[2][2]);
            c2 = cos_ap(s0 + s1);
            s0 = fmaf(h1, wh[3][1], fmaf(h0, wh[3][0], xacc[3]));
            s1 = fmaf(h3, wh[3][3], h2 * wh[3][2]);
            c3 = cos_ap(s0 + s1);
        }

        // ---- off-path: compute next step's x-part, then refill the ring ----
        {
            int slot = (t + 1) & 3;
            float xv[8] = {xa[slot].x, xa[slot].y, xa[slot].z, xa[slot].w,
                           xb[slot].x, xb[slot].y, xb[slot].z, xb[slot].w};
#pragma unroll
            for (int k = 0; k < 4; k++) {
                float q = fmaf(xv[0], wx[k][0], th[k]);
                q = fmaf(xv[1], wx[k][1], q); q = fmaf(xv[2], wx[k][2], q);
                q = fmaf(xv[3], wx[k][3], q); q = fmaf(xv[4], wx[k][4], q);
                q = fmaf(xv[5], wx[k][5], q); q = fmaf(xv[6], wx[k][6], q);
                xacc[k] = fmaf(xv[7], wx[k][7], q);
            }
            int tp = t + 5; if (tp > TT - 1) tp = TT - 1;
            size_t i = ((size_t)tp * BB + b) * 2;
            xa[slot] = xp[i]; xb[slot] = xp[i + 1];
        }

        // ---- expvals (c1 prescaled by gm): e0=c1'c2c3, e1=c0c1', e2=e1c2, e3=e1t23 ----
        float c1s = gm * c1;
        float t23 = c2 * c3;
        float e1  = c0 * c1s;
        float e0  = c1s * t23;
        float e2  = e1 * c2;
        float e3  = e1 * t23;

        // ---- gate nonlinearity: v = fma(A, tanh_pade(u), B), 1 MUFU each ----
        float v0 = fmaf(gA, tanh_pade(e0), gB);
        float v1 = fmaf(gA, tanh_pade(e1), gB);
        float v2 = fmaf(gA, tanh_pade(e2), gB);
        float v3 = fmaf(gA, tanh_pade(e3), gB);

        // ---- gather all 4 gate vectors into every lane (16 independent shfl) ----
        float tg0[4], tg1[4], tg2[4], tg3[4];
#pragma unroll
        for (int s = 0; s < 4; s++) {
            tg0[s] = __shfl_sync(0xffffffffu, v0, s, 4);
            tg1[s] = __shfl_sync(0xffffffffu, v1, s, 4);
            tg2[s] = __shfl_sync(0xffffffffu, v2, s, 4);
            tg3[s] = __shfl_sync(0xffffffffu, v3, s, 4);
        }
        // tgK[s] = gate-s value for wire K. s: 0=f, 1=i, 2=g, 3=o.

        // ---- combine (replicated in all lanes) ----
        float hn[4];
#pragma unroll
        for (int k = 0; k < 4; k++) {
            float F = (k==0)?tg0[0]:(k==1)?tg1[0]:(k==2)?tg2[0]:tg3[0];
            float I = (k==0)?tg0[1]:(k==1)?tg1[1]:(k==2)?tg2[1]:tg3[1];
            float G = (k==0)?tg0[2]:(k==1)?tg1[2]:(k==2)?tg2[2]:tg3[2];
            float O = (k==0)?tg0[3]:(k==1)?tg1[3]:(k==2)?tg2[3]:tg3[3];
            float nc = fmaf(F, cx[k], I * G);
            cx[k] = nc;
            // tanh(cx) = 1 - 2/(exp(2cx)+1)
            float E  = ex2_ap(nc * (2.0f * LOG2E));
            float r  = rcp_ap(E + 1.0f);
            float tc = fmaf(-2.0f, r, 1.0f);
            hn[k] = O * tc;                              // o * tanh(cx)
        }
        h0 = hn[0]; h1 = hn[1]; h2 = hn[2]; h3 = hn[3];

        if (g == 0)
            hout[(size_t)t * BB + b] = make_float4(h0, h1, h2, h3);
    }
}

// ---------------------------------------------------------------------------
// Kernel B: logits + log_softmax. 2 threads per row (8 tags each), low regs;
// softmax max/sum joined via shfl_xor.
// ---------------------------------------------------------------------------
__global__ void __launch_bounds__(256)
out_kernel(const float* __restrict__ w_tag,
           const float* __restrict__ b_tag,
           float* __restrict__ out)
{
    int gt   = blockIdx.x * 256 + threadIdx.x;   // 0 .. 2*NITEM-1
    int row  = gt >> 1;
    int half = gt & 1;

    const float4* wt = (const float4*)w_tag;     // 16 rows of float4
    float4 w[8]; float bt[8];
#pragma unroll
    for (int j = 0; j < 8; j++) { w[j] = wt[half*8 + j]; bt[j] = b_tag[half*8 + j]; }

    float4 hv = ((const float4*)g_h)[row];
    float lg[8];
#pragma unroll
    for (int j = 0; j < 8; j++)
        lg[j] = fmaf(w[j].w, hv.w, fmaf(w[j].z, hv.z, fmaf(w[j].y, hv.y, fmaf(w[j].x, hv.x, bt[j]))));

    float m = lg[0];
#pragma unroll
    for (int j = 1; j < 8; j++) m = fmaxf(m, lg[j]);
    m = fmaxf(m, __shfl_xor_sync(0xffffffffu, m, 1));

    float s = 0.f;
#pragma unroll
    for (int j = 0; j < 8; j++) s += ex2_ap((lg[j] - m) * LOG2E);
    s += __shfl_xor_sync(0xffffffffu, s, 1);

    float ls = fmaf(lg2_ap(s), 0.6931471805599453f, m);

    float4* o4 = (float4*)out;
    o4[(size_t)row*4 + half*2 + 0] = make_float4(lg[0]-ls, lg[1]-ls, lg[2]-ls, lg[3]-ls);
    o4[(size_t)row*4 + half*2 + 1] = make_float4(lg[4]-ls, lg[5]-ls, lg[6]-ls, lg[7]-ls);
}

extern "C" void kernel_launch(void* const* d_in, const int* in_sizes, int n_in,
                              void* d_out, int out_size)
{
    const float* x        = (const float*)d_in[0];
    const float* w_gates  = (const float*)d_in[1];
    const float* b_gates  = (const float*)d_in[2];
    const float* rx_theta = (const float*)d_in[3];
    const float* w_tag    = (const float*)d_in[4];
    const float* b_tag    = (const float*)d_in[5];

    recur_kernel<<<128, 64>>>(x, w_gates, b_gates, rx_theta);   // 8192 threads, 2 warps/block
    out_kernel<<<8192, 256>>>(w_tag, b_tag, (float*)d_out);     // 2 threads per (t,b) row
}